// round 14
// baseline (speedup 1.0000x reference)
#include <cuda_runtime.h>
#include <cuda_fp16.h>
#include <cstdint>

// Problem constants
#define Bsz   4
#define Sseq  2048
#define Dmod  512
#define Hn    8
#define NROWS (Bsz * Sseq)        // 8192
#define QKSCALE 0.125f            // 1/sqrt(64)
#define EPSV 1e-8f

// Scratch (device globals; no allocations allowed). All intermediates fp16.
__device__ unsigned short g_fused[(size_t)NROWS * Dmod];
__device__ unsigned short g_Q[(size_t)NROWS * Dmod];   // head-split [B,H,S,HD]
__device__ unsigned short g_K[(size_t)NROWS * Dmod];
__device__ unsigned short g_V[(size_t)NROWS * Dmod];
__device__ unsigned short g_att[(size_t)NROWS * Dmod]; // [B,S,D]

// ---------------------------------------------------------------------------
// Helpers
// ---------------------------------------------------------------------------
__device__ __forceinline__ uint32_t f2h2(float lo, float hi) {
    __half2 h = __floats2half2_rn(lo, hi);
    return *reinterpret_cast<uint32_t*>(&h);
}

__device__ __forceinline__ uint32_t smem_u32(const void* p) {
    uint32_t a;
    asm("{ .reg .u64 t; cvta.to.shared.u64 t, %1; cvt.u32.u64 %0, t; }"
        : "=r"(a) : "l"(p));
    return a;
}

__device__ __forceinline__ void ldsm4(uint32_t r[4], uint32_t addr) {
    asm volatile("ldmatrix.sync.aligned.m8n8.x4.shared.b16 {%0,%1,%2,%3}, [%4];"
        : "=r"(r[0]), "=r"(r[1]), "=r"(r[2]), "=r"(r[3]) : "r"(addr));
}
__device__ __forceinline__ void ldsm4t(uint32_t r[4], uint32_t addr) {
    asm volatile("ldmatrix.sync.aligned.m8n8.x4.trans.shared.b16 {%0,%1,%2,%3}, [%4];"
        : "=r"(r[0]), "=r"(r[1]), "=r"(r[2]), "=r"(r[3]) : "r"(addr));
}

// m16n8k16 f16 mma, fp32 accumulate
__device__ __forceinline__ void mma16(float d[4], const uint32_t a[4],
                                      uint32_t b0, uint32_t b1) {
    asm volatile(
        "mma.sync.aligned.m16n8k16.row.col.f32.f16.f16.f32 "
        "{%0,%1,%2,%3}, {%4,%5,%6,%7}, {%8,%9}, {%0,%1,%2,%3};"
        : "+f"(d[0]), "+f"(d[1]), "+f"(d[2]), "+f"(d[3])
        : "r"(a[0]), "r"(a[1]), "r"(a[2]), "r"(a[3]), "r"(b0), "r"(b1));
}

// ---------------------------------------------------------------------------
// FP16 tensor GEMM: C[8192 x N] = A[8192 x KTOT] @ W + bias
// Block tile 128x128, k-step 32, double-buffered smem + register prefetch,
// one __syncthreads per k-iteration.
// AH: A is fp16 in gmem (load direct).  CH: C written as fp16.
// MODE 0: plain out; MODE 1: head-split; MODE 2: merged dual (n0<512 ->
// (W1,b1,C1) else (W2,b2,C2), both head-split).
// ---------------------------------------------------------------------------
#define GA_STRIDE 80          // bytes per A smem row (64 data + 16 pad)
#define GB_STRIDE 272         // bytes per B smem row (256 data + 16 pad)
#define GA_BYTES  (128 * GA_STRIDE)
#define GB_BYTES  (32 * GB_STRIDE)
#define G_SMEM    (2 * (GA_BYTES + GB_BYTES))   // 37888

template <int KTOT, int MODE, bool AH, bool CH>
__global__ __launch_bounds__(256, 2) void gemm_f16(
    const void* __restrict__ A1v, const void* __restrict__ A2v,
    const float* __restrict__ W1, const float* __restrict__ W2,
    const float* __restrict__ b1, const float* __restrict__ b2,
    void* __restrict__ C1v, void* __restrict__ C2v)
{
    extern __shared__ char smem[];
    const uint32_t sb = smem_u32(smem);
    const int tid = threadIdx.x;
    const int wid = tid >> 5;
    const int lane = tid & 31;
    const int g = lane >> 2;
    const int tg = lane & 3;
    const int wm = (wid & 3) * 32;
    const int wn = (wid >> 2) * 64;
    const int m0 = blockIdx.y * 128;
    const int n0 = blockIdx.x * 128;

    const bool selW = (MODE == 2) && (n0 >= 512);
    const float* W = selW ? W2 : W1;
    const float* bias = selW ? b2 : b1;
    void* Cv = selW ? C2v : C1v;
    const int nc = (MODE == 2) ? (n0 & 511) : n0;

    const int jr = (lane & 7) + ((lane >> 3) & 1) * 8;
    const int jc16 = (lane >> 4) * 16;
    const int vc = (lane >> 4) * 16;

    float acc[2][8][4];
#pragma unroll
    for (int mi = 0; mi < 2; mi++)
#pragma unroll
        for (int nt = 0; nt < 8; nt++)
#pragma unroll
            for (int e = 0; e < 4; e++) acc[mi][nt][e] = 0.0f;

    float4 ra[4]; uint4 rah[2]; float4 rb[4];

    auto ldg = [&](int kt) {
        if (AH) {
            const char* A = (const char*)A1v;
#pragma unroll
            for (int it = 0; it < 2; it++) {
                int l = tid + it * 256;
                int r = l >> 2, c = l & 3;
                rah[it] = *(const uint4*)(A + (size_t)(m0 + r) * 1024 + kt * 2 + c * 16);
            }
        } else {
            const float* Asrc = (const float*)((KTOT > 512 && kt >= 512) ? A2v : A1v);
            const int kc = kt & 511;
#pragma unroll
            for (int it = 0; it < 4; it++) {
                int l = tid + it * 256;
                int r = l >> 3, c4 = l & 7;
                ra[it] = *(const float4*)&Asrc[(size_t)(m0 + r) * 512 + kc + c4 * 4];
            }
        }
#pragma unroll
        for (int it = 0; it < 4; it++) {
            int l = tid + it * 256;
            int k = l >> 5, n4 = l & 31;
            rb[it] = *(const float4*)&W[(size_t)(kt + k) * 512 + nc + n4 * 4];
        }
    };
    auto sts = [&](int buf) {
        char* Ab = smem + buf * (GA_BYTES + GB_BYTES);
        char* Bb = Ab + GA_BYTES;
        if (AH) {
#pragma unroll
            for (int it = 0; it < 2; it++) {
                int l = tid + it * 256;
                int r = l >> 2, c = l & 3;
                *(uint4*)(Ab + r * GA_STRIDE + c * 16) = rah[it];
            }
        } else {
#pragma unroll
            for (int it = 0; it < 4; it++) {
                int l = tid + it * 256;
                int r = l >> 3, c4 = l & 7;
                *(uint2*)(Ab + r * GA_STRIDE + c4 * 8) =
                    make_uint2(f2h2(ra[it].x, ra[it].y), f2h2(ra[it].z, ra[it].w));
            }
        }
#pragma unroll
        for (int it = 0; it < 4; it++) {
            int l = tid + it * 256;
            int k = l >> 5, n4 = l & 31;
            *(uint2*)(Bb + k * GB_STRIDE + n4 * 8) =
                make_uint2(f2h2(rb[it].x, rb[it].y), f2h2(rb[it].z, rb[it].w));
        }
    };
    auto comp = [&](int buf) {
        const uint32_t Ab = sb + buf * (GA_BYTES + GB_BYTES);
        const uint32_t Bb = Ab + GA_BYTES;
#pragma unroll
        for (int ks = 0; ks < 2; ks++) {
            uint32_t a0[4], a1[4];
            ldsm4(a0, Ab + (wm + jr) * GA_STRIDE + ks * 32 + jc16);
            ldsm4(a1, Ab + (wm + 16 + jr) * GA_STRIDE + ks * 32 + jc16);
#pragma unroll
            for (int np = 0; np < 4; np++) {
                uint32_t br[4];
                ldsm4t(br, Bb + (ks * 16 + jr) * GB_STRIDE + (wn + np * 16) * 2 + vc);
                mma16(acc[0][np * 2 + 0], a0, br[0], br[1]);
                mma16(acc[0][np * 2 + 1], a0, br[2], br[3]);
                mma16(acc[1][np * 2 + 0], a1, br[0], br[1]);
                mma16(acc[1][np * 2 + 1], a1, br[2], br[3]);
            }
        }
    };

    ldg(0);
    sts(0);
    __syncthreads();
    int buf = 0;

#pragma unroll 2
    for (int kt = 0; kt < KTOT; kt += 32) {
        const bool more = (kt + 32) < KTOT;
        if (more) ldg(kt + 32);
        comp(buf);
        if (more) {
            sts(buf ^ 1);
            __syncthreads();
            buf ^= 1;
        }
    }

    // Epilogue (+bias, optional head-split scatter, fp16 or fp32 out)
#pragma unroll
    for (int mi = 0; mi < 2; mi++) {
        int r0 = m0 + wm + mi * 16 + g;
#pragma unroll
        for (int nt = 0; nt < 8; nt++) {
            int c = nc + wn + nt * 8 + tg * 2;
            float bb0 = bias[c], bb1 = bias[c + 1];
#pragma unroll
            for (int rh = 0; rh < 2; rh++) {
                int row = r0 + rh * 8;
                float v0 = acc[mi][nt][rh * 2 + 0] + bb0;
                float v1 = acc[mi][nt][rh * 2 + 1] + bb1;
                size_t idx;
                if (MODE != 0) {
                    int bb = row >> 11;
                    int s = row & 2047;
                    int hh = c >> 6;
                    idx = (((size_t)(bb * Hn + hh) * Sseq + s) << 6) + (c & 63);
                } else {
                    idx = (size_t)row * 512 + c;
                }
                if (CH) {
                    *(uint32_t*)&((unsigned short*)Cv)[idx] = f2h2(v0, v1);
                } else {
                    *(float2*)&((float*)Cv)[idx] = make_float2(v0, v1);
                }
            }
        }
    }
}

// ---------------------------------------------------------------------------
// FP16 flash attention, fused mask + renormalization, fixed max = 0.
// 128 threads, 4 warps, BQ=128: warp tile 32q x 64k (each K/V fragment is
// reused by 2 A fragments -> per-CTA ldsm cut 44%). 2 CTAs/SM guaranteed.
// Q/K/V gmem are fp16; P lives in registers (no smem round trip).
// ---------------------------------------------------------------------------
#define AT_STRIDE 144
#define AT_Q 0
#define AT_K (128 * AT_STRIDE)
#define AT_V (AT_K + 64 * AT_STRIDE)
#define AT_SMEM (AT_V + 64 * AT_STRIDE)   // 36864

__global__ __launch_bounds__(128, 2) void attn_f16(const float* __restrict__ Mmask)
{
    extern __shared__ char smem[];
    const uint32_t sb = smem_u32(smem);
    const int tid = threadIdx.x;
    const int wid = tid >> 5;
    const int lane = tid & 31;
    const int g = lane >> 2;
    const int tg = lane & 3;
    const int qw = wid * 32;

    const int h = blockIdx.x;           // h fastest -> mask L2 sharing
    const int b = blockIdx.y >> 4;
    const int qt = blockIdx.y & 15;
    const int q0 = qt * 128;
    const int bh = b * Hn + h;

    const char* Qg = (const char*)g_Q + ((size_t)bh * Sseq + q0) * 128;
    const char* Kg = (const char*)g_K + (size_t)bh * Sseq * 128;
    const char* Vg = (const char*)g_V + (size_t)bh * Sseq * 128;
    const float* Mg = Mmask + ((size_t)b * Sseq + q0) * Sseq;

    const int jr = (lane & 7) + ((lane >> 3) & 1) * 8;   // A rows / trans rows
    const int jc16 = (lane >> 4) * 16;                   // A chunk
    const int kr = (lane & 7) + ((lane >> 4) & 1) * 8;   // K non-trans row
    const int kc = ((lane >> 3) & 1) * 16;               // K non-trans chunk
    const int vcb = (lane >> 4) * 16;                    // V trans col bytes

    // Q tile load (fp16) + exact /8 scale
    const __half2 qsc = __float2half2_rn(QKSCALE);
#pragma unroll
    for (int it = 0; it < 8; it++) {
        int l = tid + it * 128;
        int r = l >> 3, c = l & 7;
        uint4 v = *(const uint4*)(Qg + (size_t)r * 128 + c * 16);
        __half2* hp = (__half2*)&v;
        hp[0] = __hmul2(hp[0], qsc); hp[1] = __hmul2(hp[1], qsc);
        hp[2] = __hmul2(hp[2], qsc); hp[3] = __hmul2(hp[3], qsc);
        *(uint4*)(smem + AT_Q + r * AT_STRIDE + c * 16) = v;
    }

    float accO[2][8][4];
#pragma unroll
    for (int mi = 0; mi < 2; mi++)
#pragma unroll
        for (int nt = 0; nt < 8; nt++)
#pragma unroll
            for (int e = 0; e < 4; e++) accO[mi][nt][e] = 0.0f;
    float le[2][2] = {}, lme[2][2] = {};

    for (int k0 = 0; k0 < Sseq; k0 += 64) {
        __syncthreads();    // prior tile's ldsm reads complete

        // K, V tiles (fp16, direct copy)
#pragma unroll
        for (int it = 0; it < 4; it++) {
            int l = tid + it * 128;
            int r = l >> 3, c = l & 7;
            *(uint4*)(smem + AT_K + r * AT_STRIDE + c * 16) =
                *(const uint4*)(Kg + (size_t)(k0 + r) * 128 + c * 16);
            *(uint4*)(smem + AT_V + r * AT_STRIDE + c * 16) =
                *(const uint4*)(Vg + (size_t)(k0 + r) * 128 + c * 16);
        }

        // Mask prefetch for mi=0 rows (qw+g, qw+g+8)
        float2 mka[8], mkb[8];
#pragma unroll
        for (int nt = 0; nt < 8; nt++) {
            int col = k0 + nt * 8 + tg * 2;
            mka[nt] = *(const float2*)&Mg[(size_t)(qw + g) * Sseq + col];
            mkb[nt] = *(const float2*)&Mg[(size_t)(qw + g + 8) * Sseq + col];
        }
        __syncthreads();

        // QK^T: S[32 x 64] per warp (2 m-frags share each K fragment)
        float S0[8][4], S1[8][4];
#pragma unroll
        for (int nt = 0; nt < 8; nt++)
#pragma unroll
            for (int e = 0; e < 4; e++) { S0[nt][e] = 0.0f; S1[nt][e] = 0.0f; }

#pragma unroll
        for (int ks = 0; ks < 4; ks++) {
            uint32_t a0[4], a1[4];
            ldsm4(a0, sb + AT_Q + (qw + jr) * AT_STRIDE + ks * 32 + jc16);
            ldsm4(a1, sb + AT_Q + (qw + 16 + jr) * AT_STRIDE + ks * 32 + jc16);
#pragma unroll
            for (int np = 0; np < 4; np++) {
                uint32_t br[4];
                ldsm4(br, sb + AT_K + (np * 16 + kr) * AT_STRIDE + ks * 32 + kc);
                mma16(S0[np * 2 + 0], a0, br[0], br[1]);
                mma16(S0[np * 2 + 1], a0, br[2], br[3]);
                mma16(S1[np * 2 + 0], a1, br[0], br[1]);
                mma16(S1[np * 2 + 1], a1, br[2], br[3]);
            }
        }

        // Mask for mi=1 rows (qw+16+g, qw+24+g)
        float2 nka[8], nkb[8];
#pragma unroll
        for (int nt = 0; nt < 8; nt++) {
            int col = k0 + nt * 8 + tg * 2;
            nka[nt] = *(const float2*)&Mg[(size_t)(qw + 16 + g) * Sseq + col];
            nkb[nt] = *(const float2*)&Mg[(size_t)(qw + 24 + g) * Sseq + col];
        }

        // Masked exp (fixed max = 0); P -> half2 registers
        uint32_t paL0[8], paH0[8], paL1[8], paH1[8];
        float s00 = 0.0f, p00s = 0.0f, s01 = 0.0f, p01s = 0.0f;
        float s10 = 0.0f, p10s = 0.0f, s11 = 0.0f, p11s = 0.0f;
#pragma unroll
        for (int nt = 0; nt < 8; nt++) {
            float e0 = __expf(S0[nt][0] * mka[nt].x);
            float e1 = __expf(S0[nt][1] * mka[nt].y);
            float e2 = __expf(S0[nt][2] * mkb[nt].x);
            float e3 = __expf(S0[nt][3] * mkb[nt].y);
            float q0v = e0 * mka[nt].x, q1v = e1 * mka[nt].y;
            float q2v = e2 * mkb[nt].x, q3v = e3 * mkb[nt].y;
            s00 += e0 + e1; p00s += q0v + q1v;
            s01 += e2 + e3; p01s += q2v + q3v;
            paL0[nt] = f2h2(q0v, q1v);
            paH0[nt] = f2h2(q2v, q3v);
        }
#pragma unroll
        for (int nt = 0; nt < 8; nt++) {
            float e0 = __expf(S1[nt][0] * nka[nt].x);
            float e1 = __expf(S1[nt][1] * nka[nt].y);
            float e2 = __expf(S1[nt][2] * nkb[nt].x);
            float e3 = __expf(S1[nt][3] * nkb[nt].y);
            float q0v = e0 * nka[nt].x, q1v = e1 * nka[nt].y;
            float q2v = e2 * nkb[nt].x, q3v = e3 * nkb[nt].y;
            s10 += e0 + e1; p10s += q0v + q1v;
            s11 += e2 + e3; p11s += q2v + q3v;
            paL1[nt] = f2h2(q0v, q1v);
            paH1[nt] = f2h2(q2v, q3v);
        }
#pragma unroll
        for (int o = 1; o <= 2; o <<= 1) {
            s00 += __shfl_xor_sync(0xffffffffu, s00, o);
            p00s += __shfl_xor_sync(0xffffffffu, p00s, o);
            s01 += __shfl_xor_sync(0xffffffffu, s01, o);
            p01s += __shfl_xor_sync(0xffffffffu, p01s, o);
            s10 += __shfl_xor_sync(0xffffffffu, s10, o);
            p10s += __shfl_xor_sync(0xffffffffu, p10s, o);
            s11 += __shfl_xor_sync(0xffffffffu, s11, o);
            p11s += __shfl_xor_sync(0xffffffffu, p11s, o);
        }
        le[0][0] += s00; lme[0][0] += p00s;
        le[0][1] += s01; lme[0][1] += p01s;
        le[1][0] += s10; lme[1][0] += p10s;
        le[1][1] += s11; lme[1][1] += p11s;

        // PV: O[32 x 64] += P[32 x 64] @ V[64 x 64]; V frags shared by 2 mi
#pragma unroll
        for (int ks = 0; ks < 4; ks++) {
            uint32_t a0[4], a1[4];
            a0[0] = paL0[ks * 2 + 0]; a0[1] = paH0[ks * 2 + 0];
            a0[2] = paL0[ks * 2 + 1]; a0[3] = paH0[ks * 2 + 1];
            a1[0] = paL1[ks * 2 + 0]; a1[1] = paH1[ks * 2 + 0];
            a1[2] = paL1[ks * 2 + 1]; a1[3] = paH1[ks * 2 + 1];
#pragma unroll
            for (int np = 0; np < 4; np++) {
                uint32_t br[4];
                ldsm4t(br, sb + AT_V + (ks * 16 + jr) * AT_STRIDE + np * 32 + vcb);
                mma16(accO[0][np * 2 + 0], a0, br[0], br[1]);
                mma16(accO[0][np * 2 + 1], a0, br[2], br[3]);
                mma16(accO[1][np * 2 + 0], a1, br[0], br[1]);
                mma16(accO[1][np * 2 + 1], a1, br[2], br[3]);
            }
        }
    }

    // Normalize and write [B,S,D] as fp16
    unsigned short* Og = g_att;
#pragma unroll
    for (int mi = 0; mi < 2; mi++) {
        float inv0 = 1.0f / (lme[mi][0] + EPSV * le[mi][0]);
        float inv1 = 1.0f / (lme[mi][1] + EPSV * le[mi][1]);
        size_t row0 = (size_t)b * Sseq + q0 + qw + mi * 16 + g;
        size_t row1 = row0 + 8;
#pragma unroll
        for (int nt = 0; nt < 8; nt++) {
            int col = h * 64 + nt * 8 + tg * 2;
            *(uint32_t*)&Og[row0 * 512 + col] =
                f2h2(accO[mi][nt][0] * inv0, accO[mi][nt][1] * inv0);
            *(uint32_t*)&Og[row1 * 512 + col] =
                f2h2(accO[mi][nt][2] * inv1, accO[mi][nt][3] * inv1);
        }
    }
}

// ---------------------------------------------------------------------------
extern "C" void kernel_launch(void* const* d_in, const int* in_sizes, int n_in,
                              void* d_out, int out_size)
{
    const float* gene = (const float*)d_in[0];
    const float* expr = (const float*)d_in[1];
    const float* Mmask = (const float*)d_in[2];
    const float* Wf = (const float*)d_in[3];
    const float* bf = (const float*)d_in[4];
    const float* WQ = (const float*)d_in[5];
    const float* bQ = (const float*)d_in[6];
    const float* WK = (const float*)d_in[7];
    const float* bK = (const float*)d_in[8];
    const float* WV = (const float*)d_in[9];
    const float* bV = (const float*)d_in[10];
    const float* WO = (const float*)d_in[11];
    const float* bO = (const float*)d_in[12];
    float* out = (float*)d_out;

    void *pf, *pq, *pk, *pv, *pa;
    cudaGetSymbolAddress(&pf, g_fused);
    cudaGetSymbolAddress(&pq, g_Q);
    cudaGetSymbolAddress(&pk, g_K);
    cudaGetSymbolAddress(&pv, g_V);
    cudaGetSymbolAddress(&pa, g_att);

    static bool attr_set = false;
    if (!attr_set) {
        cudaFuncSetAttribute(gemm_f16<1024, 0, false, true>,
                             cudaFuncAttributeMaxDynamicSharedMemorySize, G_SMEM);
        cudaFuncSetAttribute(gemm_f16<512, 2, true, true>,
                             cudaFuncAttributeMaxDynamicSharedMemorySize, G_SMEM);
        cudaFuncSetAttribute(gemm_f16<512, 1, false, true>,
                             cudaFuncAttributeMaxDynamicSharedMemorySize, G_SMEM);
        cudaFuncSetAttribute(gemm_f16<512, 0, true, false>,
                             cudaFuncAttributeMaxDynamicSharedMemorySize, G_SMEM);
        cudaFuncSetAttribute(attn_f16,
                             cudaFuncAttributeMaxDynamicSharedMemorySize, AT_SMEM);
        attr_set = true;
    }

    // fused = concat(gene, expr) @ W_fused + b_fused  (K=1024, fp16 out)
    gemm_f16<1024, 0, false, true><<<dim3(4, 64), 256, G_SMEM>>>(
        gene, expr, Wf, nullptr, bf, nullptr, pf, nullptr);

    // Q and K from fused (fp16 A) in ONE merged N=1024 GEMM (head-split fp16)
    gemm_f16<512, 2, true, true><<<dim3(8, 64), 256, G_SMEM>>>(
        pf, nullptr, WQ, WK, bQ, bK, pq, pk);

    // V from expr (fp32 A, head-split fp16 out)
    gemm_f16<512, 1, false, true><<<dim3(4, 64), 256, G_SMEM>>>(
        expr, nullptr, WV, nullptr, bV, nullptr, pv, nullptr);

    // Attention (h fastest for mask L2 reuse); 128 threads, BQ=128
    attn_f16<<<dim3(Hn, Bsz * 16), 128, AT_SMEM>>>(Mmask);

    // Output projection (fp16 A -> fp32 out)
    gemm_f16<512, 0, true, false><<<dim3(4, 64), 256, G_SMEM>>>(
        pa, nullptr, WO, nullptr, bO, nullptr, out, nullptr);
}